// round 17
// baseline (speedup 1.0000x reference)
#include <cuda_runtime.h>
#include <cuda.h>
#include <cuda_fp16.h>
#include <cstdint>
#include <cstring>

// Conv 7x7 C=1 implicit GEMM via mma.sync. R17 (= R16 resubmit after infra
// flake): double-buffered C tile so the TMA bulk-tensor store drain (SMEM
// read) overlaps the next tile's compute (wait_group.read 1 at loop top --
// removes the per-tile drain bubble). Single-pass fp16 (rel_err 2.8e-4),
// B frags register-resident, cp.async double-buffered input, inline
// f32->fp16 im2col, SW128 C scatter.

#define HH 224
#define WW 224
#define HhW (HH * WW)
#define NB 32
#define NF 64
#define THREADS 256
#define NCTA 296                    // 2 * 148, persistent
#define TY 4
#define TX 32
#define TPI 392                     // 56 * 7 tiles per image
#define NTILES (NB * TPI)           // 12544
#define RAWR 10
#define RAWC 38
#define RAWN (RAWR * RAWC)          // 380

// SMEM layout (bytes). A rows: 72 halves = 144B stride.
#define S_AH 0                      // 128 x 144 = 18432
#define S_B  18432                  // 64 x 144 = 9216 -> 27648
#define S_RF 27648                  // raw f32, 2 x 1520 -> 30688 (+pad)
#define S_C  30720                  // C tiles: 2 x 32768 (1024-aligned)
#define S_TOT 96256

// TMA swizzle (SW128): bits[6:4] ^= bits[9:7]
#define SWZ(o) ((o) ^ (((o) >> 3) & 0x70))

__device__ __align__(128) unsigned long long g_tmap[16];

struct TMapBits { unsigned long long w[16]; };

__global__ void tmap_setup_kernel(TMapBits m) {
    if (threadIdx.x < 16) g_tmap[threadIdx.x] = m.w[threadIdx.x];
    __syncthreads();
    if (threadIdx.x == 0)
        asm volatile("fence.proxy.tensormap::generic.release.gpu;" ::: "memory");
}

__device__ __forceinline__ uint32_t smem_u32(const void* p) {
    uint32_t a;
    asm("{ .reg .u64 t; cvta.to.shared.u64 t, %1; cvt.u32.u64 %0, t; }" : "=r"(a) : "l"(p));
    return a;
}
__device__ __forceinline__ void sts16(uint32_t a, uint32_t v) {
    asm volatile("st.shared.u16 [%0], %1;" :: "r"(a), "r"(v) : "memory");
}
__device__ __forceinline__ void sts32f(uint32_t a, float v) {
    asm volatile("st.shared.f32 [%0], %1;" :: "r"(a), "f"(v) : "memory");
}
__device__ __forceinline__ float lds32f(uint32_t a) {
    float v;
    asm volatile("ld.shared.f32 %0, [%1];" : "=f"(v) : "r"(a));
    return v;
}
__device__ __forceinline__ void sts128(uint32_t a, uint32_t r0, uint32_t r1,
                                       uint32_t r2, uint32_t r3) {
    asm volatile("st.shared.v4.b32 [%0], {%1, %2, %3, %4};"
                 :: "r"(a), "r"(r0), "r"(r1), "r"(r2), "r"(r3) : "memory");
}
__device__ __forceinline__ void cpasync4(uint32_t dst, const void* src, uint32_t sz) {
    asm volatile("cp.async.ca.shared.global [%0], [%1], 4, %2;"
                 :: "r"(dst), "l"(src), "r"(sz) : "memory");
}
#define CP_COMMIT() asm volatile("cp.async.commit_group;" ::: "memory")
#define CP_WAIT0()  asm volatile("cp.async.wait_group 0;" ::: "memory")

#define LDSM4(r, addr) \
    asm volatile("ldmatrix.sync.aligned.m8n8.x4.shared.b16 {%0,%1,%2,%3}, [%4];" \
        : "=r"((r)[0]), "=r"((r)[1]), "=r"((r)[2]), "=r"((r)[3]) : "r"(addr))

#define MMA16816(c, a, bb0, bb1) \
    asm volatile("mma.sync.aligned.m16n8k16.row.col.f32.f16.f16.f32 " \
        "{%0,%1,%2,%3}, {%4,%5,%6,%7}, {%8,%9}, {%0,%1,%2,%3};" \
        : "+f"((c)[0]), "+f"((c)[1]), "+f"((c)[2]), "+f"((c)[3]) \
        : "r"((a)[0]), "r"((a)[1]), "r"((a)[2]), "r"((a)[3]), "r"(bb0), "r"(bb1))

__device__ __forceinline__ uint32_t f22h(float a, float b) {
    __half2 h = __floats2half2_rn(a, b);     // low = a, high = b
    return *reinterpret_cast<uint32_t*>(&h);
}

__global__ void __launch_bounds__(THREADS, 2)
conv7x7_mma8_kernel(const float* __restrict__ in,
                    const float* __restrict__ wk) {
    extern __shared__ char smem[];
    const uint32_t sb = smem_u32(smem);
    const int tid = threadIdx.x;
    const int lane = tid & 31;
    const int wid = tid >> 5;

    if (tid == 0)
        asm volatile("fence.proxy.tensormap::generic.acquire.gpu [%0], 128;"
                     :: "l"(g_tmap) : "memory");

    // ---- one-time init: zero A + B + raw regions (padding stays zero) ----
    for (int i = tid * 16; i < S_C; i += THREADS * 16)
        sts128(sb + i, 0u, 0u, 0u, 0u);
    __syncthreads();

    // ---- weights -> B fp16 (RN), [f][k=ky*8+kx], row stride 144B ----
    for (int i = tid; i < NF * 49; i += THREADS) {
        int f = i / 49, q = i - f * 49;
        int ky = q / 7, kx = q - ky * 7;
        uint32_t h = (uint32_t)__half_as_ushort(__float2half(wk[i]));
        sts16(sb + S_B + (uint32_t)(f * 144 + (ky * 8 + kx) * 2), h);
    }
    __syncthreads();

    // ---- per-warp ldmatrix lane offsets ----
    const int wm = wid & 3;          // m-tile (4) == dy of this warp's pixels
    const int wn = wid >> 2;         // n-tile (2)
    const uint32_t aoff = (uint32_t)((wm * 32 + (lane & 15)) * 144 + (lane >> 4) * 16);
    const uint32_t boff = (uint32_t)((wn * 32 + (lane & 7) + ((lane >> 4) & 1) * 8) * 144
                                     + ((lane >> 3) & 1) * 16);

    // ---- B fragments: register-resident for the whole kernel ----
    uint32_t bf[4][8];
    #pragma unroll
    for (int k = 0; k < 4; k++) {
        LDSM4(&bf[k][0], sb + S_B + boff + k * 32);          // n-tiles 0,1
        LDSM4(&bf[k][4], sb + S_B + boff + 2304 + k * 32);   // n-tiles 2,3
    }

    // ---- raw issue helper (cp.async f32, zfill OOB) ----
    auto issue_raw = [&](int tile, int buf) {
        const int b = tile / TPI;
        const int rem = tile - b * TPI;
        const int yp = rem / 7;
        const int xh = rem - yp * 7;
        const int y0 = yp * TY, x0 = xh * TX;
        const float* inb = in + (size_t)b * HhW;
        #pragma unroll
        for (int it = 0; it < 2; it++) {
            int i = tid + it * THREADS;
            if (i < RAWN) {
                int r = i / RAWC, c = i - r * RAWC;
                int gy = y0 - 3 + r, gx = x0 - 3 + c;
                bool ok = (gy >= 0 && gy < HH && gx >= 0 && gx < WW);
                const float* src = ok ? (inb + gy * WW + gx) : inb;
                cpasync4(sb + S_RF + buf * 1520 + (uint32_t)i * 4, src, ok ? 4u : 0u);
            }
        }
    };

    int buf = 0;
    int cbuf = 0;
    issue_raw(blockIdx.x, 0);
    CP_COMMIT();

    for (int tile = blockIdx.x; tile < NTILES; tile += NCTA) {
        const int b = tile / TPI;
        const int rem = tile - b * TPI;
        const int yp = rem / 7;
        const int xh = rem - yp * 7;
        const int y0 = yp * TY, x0 = xh * TX;

        CP_WAIT0();
        if (tid == 0)
            asm volatile("cp.async.bulk.wait_group.read 1;" ::: "memory");
        __syncthreads();   // raw[buf] ready; C[cbuf] drained; prev A reads done

        // prefetch next tile's raw into other buffer (overlaps im2col + MMA)
        {
            int nt = tile + NCTA;
            if (nt < NTILES) issue_raw(nt, buf ^ 1);
            CP_COMMIT();
        }

        // ---- phase 1: im2col, inline f32 -> fp16 RN ----
        {
            const int m = tid & 127;          // m = dy*32 + x
            const int half = tid >> 7;
            const int dy = m >> 5, x = m & 31;
            const int ky0 = half ? 4 : 0, ky1 = half ? 7 : 4;
            const uint32_t ah = sb + S_AH + (uint32_t)m * 144;
            const uint32_t rb = sb + S_RF + (uint32_t)buf * 1520;
            for (int ky = ky0; ky < ky1; ky++) {
                uint32_t ra = rb + (uint32_t)(((dy + ky) * RAWC + x) * 4);
                float f0 = lds32f(ra + 0),  f1 = lds32f(ra + 4);
                float f2 = lds32f(ra + 8),  f3 = lds32f(ra + 12);
                float f4 = lds32f(ra + 16), f5 = lds32f(ra + 20);
                float f6 = lds32f(ra + 24), f7 = lds32f(ra + 28);
                sts128(ah + ky * 16,
                       f22h(f0, f1), f22h(f2, f3),
                       f22h(f4, f5), f22h(f6, f7));
            }
        }
        __syncthreads();   // A ready

        // ---- phase 2: single-pass warp MMA (B frags resident) ----
        float acc[32];
        #pragma unroll
        for (int i = 0; i < 32; i++) acc[i] = 0.0f;

        {
            const uint32_t Ab = sb + S_AH + aoff;
            #pragma unroll
            for (int k = 0; k < 4; k++) {
                uint32_t a0[4], a1[4];
                LDSM4(a0, Ab + k * 32);            // m-tile 0
                LDSM4(a1, Ab + 2304 + k * 32);     // m-tile 1
                MMA16816(acc + 0,  a0, bf[k][0], bf[k][1]);
                MMA16816(acc + 4,  a0, bf[k][2], bf[k][3]);
                MMA16816(acc + 8,  a0, bf[k][4], bf[k][5]);
                MMA16816(acc + 12, a0, bf[k][6], bf[k][7]);
                MMA16816(acc + 16, a1, bf[k][0], bf[k][1]);
                MMA16816(acc + 20, a1, bf[k][2], bf[k][3]);
                MMA16816(acc + 24, a1, bf[k][4], bf[k][5]);
                MMA16816(acc + 28, a1, bf[k][6], bf[k][7]);
            }
        }

        // ---- phase 3: STS C tile, SW128-swizzled [dy][n][x] (conflict-free) ----
        {
            const int tg = lane & 3, gp = lane >> 2;
            const uint32_t cb = sb + S_C + (uint32_t)(cbuf * 32768 + wm * 8192);
            #pragma unroll
            for (int in_ = 0; in_ < 4; in_++) {
                #pragma unroll
                for (int im = 0; im < 2; im++) {
                    const float* a = &acc[(im * 4 + in_) * 4];
                    uint32_t o00 = (uint32_t)((wn * 32 + in_ * 8 + 2 * tg) * 128
                                              + (im * 16 + gp) * 4);
                    sts32f(cb + SWZ(o00), a[0]);            // (n0,   x)
                    sts32f(cb + SWZ(o00 + 128), a[1]);      // (n0+1, x)
                    sts32f(cb + SWZ(o00 + 32), a[2]);       // (n0,   x+8)
                    sts32f(cb + SWZ(o00 + 160), a[3]);      // (n0+1, x+8)
                }
            }
        }
        __syncthreads();   // C[cbuf] complete

        // ---- phase 4: TMA bulk store SMEM -> gmem (engine, bypasses L1) ----
        if (tid == 0) {
            asm volatile("fence.proxy.async.shared::cta;" ::: "memory");
            asm volatile(
                "cp.async.bulk.tensor.3d.global.shared::cta.tile.bulk_group "
                "[%0, {%1, %2, %3}], [%4];"
                :: "l"(g_tmap), "r"(x0), "r"(b * NF), "r"(y0),
                   "r"(sb + S_C + (uint32_t)(cbuf * 32768)) : "memory");
            asm volatile("cp.async.bulk.commit_group;" ::: "memory");
        }
        buf ^= 1;
        cbuf ^= 1;
        // loop-top wait_group.read 1 + barrier protect C[cbuf] and A reuse
    }

    if (tid == 0)
        asm volatile("cp.async.bulk.wait_group 0;" ::: "memory");
}

typedef CUresult (*PFN_tmapEncode)(
    CUtensorMap*, CUtensorMapDataType, cuuint32_t, void*,
    const cuuint64_t*, const cuuint64_t*, const cuuint32_t*, const cuuint32_t*,
    CUtensorMapInterleave, CUtensorMapSwizzle, CUtensorMapL2promotion,
    CUtensorMapFloatOOBfill);

extern "C" void kernel_launch(void* const* d_in, const int* in_sizes, int n_in,
                              void* d_out, int out_size) {
    const float* x = (const float*)d_in[0];   // (32,1,224,224) f32
    const float* k = (const float*)d_in[1];   // (64,7,7) f32

    // ---- build tensor map for out (x, plane=b*64+n, y), box (32, 64, 4) ----
    void* fp = nullptr;
    cudaDriverEntryPointQueryResult qr;
    cudaGetDriverEntryPoint("cuTensorMapEncodeTiled", &fp,
                            cudaEnableDefault, &qr);
    static CUtensorMap tmap;
    cuuint64_t dims[3]    = {224, (cuuint64_t)NB * NF, 224};
    cuuint64_t strides[2] = {(cuuint64_t)HhW * 4, 224 * 4};  // plane, y (bytes)
    cuuint32_t box[3]     = {32, 64, 4};
    cuuint32_t estr[3]    = {1, 1, 1};
    ((PFN_tmapEncode)fp)(&tmap, CU_TENSOR_MAP_DATA_TYPE_FLOAT32, 3, d_out,
                         dims, strides, box, estr,
                         CU_TENSOR_MAP_INTERLEAVE_NONE,
                         CU_TENSOR_MAP_SWIZZLE_128B,
                         CU_TENSOR_MAP_L2_PROMOTION_L2_128B,
                         CU_TENSOR_MAP_FLOAT_OOB_FILL_NONE);

    TMapBits bits;
    memcpy(&bits, &tmap, sizeof(bits));
    tmap_setup_kernel<<<1, 32>>>(bits);

    cudaFuncSetAttribute(conv7x7_mma8_kernel,
                         cudaFuncAttributeMaxDynamicSharedMemorySize, S_TOT);
    conv7x7_mma8_kernel<<<NCTA, THREADS, S_TOT>>>(x, k);
}